// round 10
// baseline (speedup 1.0000x reference)
#include <cuda_runtime.h>
#include <cstdint>
#include <cfloat>

#define NPTS 8192
#define BMAX 8
#define NB   512                      // z-buckets per set-batch
#define NSB  (2 * BMAX)
#define QT   256                      // threads per query block (8 autonomous warps)
#define PT   512                      // prep threads
#define ZMIN (-6.0f)
#define ZSPAN 12.0f
#define NQBLK (NPTS / QT * BMAX * 2)  // 512 query blocks

// ---- scratch (device globals; no allocation) --------------------------------
__device__ float4 g_sorted[NSB * NPTS];        // z-bucket-sorted, w = |p|^2
__device__ int    g_cellstart[NSB * (NB + 1)];
__device__ float  g_part[NQBLK];
__device__ unsigned int g_cnt;                 // zero-init; reset each run

__device__ __forceinline__ int zbucket(float z) {
    int c = (int)((z - ZMIN) * (NB / ZSPAN));
    return min(NB - 1, max(0, c));
}

// ==== K1: per set-batch: smem hist -> smem scan -> scatter ===================
__global__ __launch_bounds__(PT)
void k_prep(const float* __restrict__ preds,
            const float* __restrict__ gts, int B) {
    const int sb  = blockIdx.x;
    const int set = sb / B, b = sb - set * B;
    const float* P = (set == 0 ? preds : gts) + (size_t)b * 3 * NPTS;
    const int t = threadIdx.x;

    __shared__ int s_cnt[NB];
    __shared__ int s_off[NB];

    s_cnt[t] = 0;
    __syncthreads();

    for (int i = t; i < NPTS; i += PT) {
        float z = P[2 * NPTS + i];
        atomicAdd(&s_cnt[zbucket(z)], 1);
    }
    __syncthreads();

    // inclusive Hillis-Steele scan over NB(=PT) elements
    int own = s_cnt[t];
    s_off[t] = own;
    __syncthreads();
    for (int off = 1; off < NB; off <<= 1) {
        int v = (t >= off) ? s_off[t - off] : 0;
        __syncthreads();
        s_off[t] += v;
        __syncthreads();
    }
    int incl = s_off[t];
    int excl = incl - own;

    g_cellstart[sb * (NB + 1) + t] = excl;
    if (t == NB - 1) g_cellstart[sb * (NB + 1) + NB] = incl;  // = NPTS

    s_cnt[t] = excl;
    __syncthreads();

    float4* dst = g_sorted + (size_t)sb * NPTS;
    for (int i = t; i < NPTS; i += PT) {
        float x = P[i], y = P[NPTS + i], z = P[2 * NPTS + i];
        int pos = atomicAdd(&s_cnt[zbucket(z)], 1);
        dst[pos] = make_float4(x, y, z, x * x + y * y + z * z);
    }
}

// ==== padding so k_query is the 4th launch (ncu profiles launch #4) ==========
__global__ void k_nop() {}

// ==== K2: warp-autonomous sort-sweep exact NN ================================
__global__ __launch_bounds__(QT)
void k_query(float* __restrict__ out, int B) {
    const int b   = blockIdx.y;
    const int dir = blockIdx.z;
    const int t   = threadIdx.x;

    const int sbq = (dir == 0 ? 0 : B) + b;   // queries
    const int sbr = (dir == 0 ? B : 0) + b;   // references (other set)

    const int*    cs  = g_cellstart + (size_t)sbr * (NB + 1);
    const float4* rpt = g_sorted + (size_t)sbr * NPTS;

    // one query per thread; warp owns 32 consecutive z-sorted queries
    const int qidx = blockIdx.x * QT + t;
    float4 q = __ldg(&g_sorted[(size_t)sbq * NPTS + qidx]);
    const float nx = -2.f * q.x, ny = -2.f * q.y, nz = -2.f * q.z;
    const float zq = q.z;
    const int myb = zbucket(zq);

    // warp-uniform initial window: lanes are sorted, so lane0=min, lane31=max
    const unsigned FULL = 0xffffffffu;
    int wlo = max(__shfl_sync(FULL, myb, 0)  - 1, 0);
    int whi = min(__shfl_sync(FULL, myb, 31) + 1, NB - 1);

    float mA = FLT_MAX, mB = FLT_MAX;   // alternating min accumulators

    // warp-uniform candidate run [beg, end): uniform-address LDG broadcast
    auto evalrun = [&](int beg, int end) {
        int k = beg;
        for (; k + 4 <= end; k += 4) {
            float4 p0 = __ldg(rpt + k);
            float4 p1 = __ldg(rpt + k + 1);
            float4 p2 = __ldg(rpt + k + 2);
            float4 p3 = __ldg(rpt + k + 3);
            mA = fminf(mA, fmaf(nx, p0.x, fmaf(ny, p0.y, fmaf(nz, p0.z, p0.w))));
            mB = fminf(mB, fmaf(nx, p1.x, fmaf(ny, p1.y, fmaf(nz, p1.z, p1.w))));
            mA = fminf(mA, fmaf(nx, p2.x, fmaf(ny, p2.y, fmaf(nz, p2.z, p2.w))));
            mB = fminf(mB, fmaf(nx, p3.x, fmaf(ny, p3.y, fmaf(nz, p3.z, p3.w))));
        }
        for (; k < end; k++) {
            float4 p = __ldg(rpt + k);
            mA = fminf(mA, fmaf(nx, p.x, fmaf(ny, p.y, fmaf(nz, p.z, p.w))));
        }
    };

    evalrun(__ldg(cs + wlo), __ldg(cs + whi + 1));

    const float W = ZSPAN / NB;
    for (;;) {
        float b2 = fminf(mA, mB) + q.w;           // best squared distance
        float le = ZMIN + wlo * W;
        float re = ZMIN + (whi + 1) * W;
        float gl = zq - le, gr = re - zq;
        bool myL = (wlo == 0)      || (gl * gl >= b2);
        bool myR = (whi == NB - 1) || (gr * gr >= b2);
        bool dL = __all_sync(FULL, myL);
        bool dR = __all_sync(FULL, myR);
        if (dL && dR) break;
        if (!dL) {   // expand left one bucket
            wlo--;
            evalrun(__ldg(cs + wlo), __ldg(cs + wlo + 1));
        }
        if (!dR) {   // expand right one bucket
            whi++;
            evalrun(__ldg(cs + whi), __ldg(cs + whi + 1));
        }
    }

    // deterministic-shape block tree reduction (single sync point per block)
    __shared__ float sred[QT];
    __shared__ bool  is_last;
    sred[t] = fminf(mA, mB) + q.w;
    __syncthreads();
    for (int s = QT / 2; s > 0; s >>= 1) {
        if (t < s) sred[t] += sred[t + s];
        __syncthreads();
    }

    const int nblk = gridDim.x * gridDim.y * gridDim.z;
    if (t == 0) {
        int bid = (blockIdx.z * gridDim.y + blockIdx.y) * gridDim.x + blockIdx.x;
        g_part[bid] = sred[0];
        __threadfence();
        unsigned int r = atomicAdd(&g_cnt, 1u);
        is_last = (r == (unsigned)(nblk - 1));
    }
    __syncthreads();

    if (is_last) {   // fixed-order final sum (value independent of arrival order)
        float v = 0.f;
        volatile float* vp = g_part;
        for (int i = t; i < nblk; i += QT) v += vp[i];
        sred[t] = v;
        __syncthreads();
        for (int s = QT / 2; s > 0; s >>= 1) {
            if (t < s) sred[t] += sred[t + s];
            __syncthreads();
        }
        if (t == 0) {
            out[0] = sred[0];
            g_cnt = 0;   // reset for next graph replay
        }
    }
}

extern "C" void kernel_launch(void* const* d_in, const int* in_sizes, int n_in,
                              void* d_out, int out_size) {
    const float* preds = (const float*)d_in[0];
    const float* gts   = (const float*)d_in[1];
    float* out = (float*)d_out;
    const int B = in_sizes[0] / (3 * NPTS);  // 8 here

    k_prep<<<2 * B, PT>>>(preds, gts, B);
    k_nop<<<1, 32>>>();
    k_nop<<<1, 32>>>();
    dim3 grid(NPTS / QT, B, 2);              // (32, 8, 2) = 512 blocks
    k_query<<<grid, QT>>>(out, B);           // <- 4th launch: gets the ncu profile
}

// round 11
// speedup vs baseline: 2.2934x; 2.2934x over previous
#include <cuda_runtime.h>
#include <cstdint>
#include <cfloat>

#define NPTS 8192
#define BMAX 8
#define NB   256                      // z-buckets per set-batch
#define NSB  (2 * BMAX)
#define QT   256                      // 8 autonomous warps per block
#define NW   (QT / 32)
#define CAPW 256                      // per-warp smem slice (float4) = 4KB
#define ZMIN (-6.0f)
#define ZSPAN 12.0f
#define NQBLK (NPTS / QT * BMAX * 2)  // 512 query blocks

// ---- scratch (device globals; no allocation) --------------------------------
__device__ float4 g_sorted[NSB * NPTS];        // z-bucket-sorted, w = |p|^2
__device__ int    g_cellstart[NSB * (NB + 1)];
__device__ float  g_part[NQBLK];
__device__ unsigned int g_cnt;                 // zero-init; reset each run

__device__ __forceinline__ int zbucket(float z) {
    int c = (int)((z - ZMIN) * (NB / ZSPAN));
    return min(NB - 1, max(0, c));
}

// ==== K1: per set-batch: smem hist -> smem scan -> scatter ===================
__global__ __launch_bounds__(256)
void k_prep(const float* __restrict__ preds,
            const float* __restrict__ gts, int B) {
    const int sb  = blockIdx.x;
    const int set = sb / B, b = sb - set * B;
    const float* P = (set == 0 ? preds : gts) + (size_t)b * 3 * NPTS;
    const int t = threadIdx.x;

    __shared__ int s_cnt[NB];
    __shared__ int s_off[NB];

    s_cnt[t] = 0;
    __syncthreads();

    for (int i = t; i < NPTS; i += 256) {
        float z = P[2 * NPTS + i];
        atomicAdd(&s_cnt[zbucket(z)], 1);
    }
    __syncthreads();

    int own = s_cnt[t];
    s_off[t] = own;
    __syncthreads();
    for (int off = 1; off < NB; off <<= 1) {
        int v = (t >= off) ? s_off[t - off] : 0;
        __syncthreads();
        s_off[t] += v;
        __syncthreads();
    }
    int incl = s_off[t];
    int excl = incl - own;

    g_cellstart[sb * (NB + 1) + t] = excl;
    if (t == NB - 1) g_cellstart[sb * (NB + 1) + NB] = incl;  // = NPTS

    s_cnt[t] = excl;
    __syncthreads();

    float4* dst = g_sorted + (size_t)sb * NPTS;
    for (int i = t; i < NPTS; i += 256) {
        float x = P[i], y = P[NPTS + i], z = P[2 * NPTS + i];
        int pos = atomicAdd(&s_cnt[zbucket(z)], 1);
        dst[pos] = make_float4(x, y, z, x * x + y * y + z * z);
    }
}

// ==== padding so k_query is the 4th launch (ncu profiles launch #4) ==========
__global__ void k_nop() {}

// ==== K2: warp-autonomous windows, per-warp smem staging =====================
__global__ __launch_bounds__(QT)
void k_query(float* __restrict__ out, int B) {
    const int b    = blockIdx.y;
    const int dir  = blockIdx.z;
    const int t    = threadIdx.x;
    const int w    = t >> 5;
    const int lane = t & 31;

    const int sbq = (dir == 0 ? 0 : B) + b;   // queries
    const int sbr = (dir == 0 ? B : 0) + b;   // references (other set)

    const int*    cs  = g_cellstart + (size_t)sbr * (NB + 1);
    const float4* rpt = g_sorted + (size_t)sbr * NPTS;

    // one query per thread; each warp owns 32 consecutive z-sorted queries
    const int qidx = blockIdx.x * QT + t;
    float4 q = __ldg(&g_sorted[(size_t)sbq * NPTS + qidx]);
    const float nx = -2.f * q.x, ny = -2.f * q.y, nz = -2.f * q.z;
    const float zq = q.z;
    const int myb = zbucket(zq);

    __shared__ float4 sbuf[NW][CAPW];   // private slice per warp

    const unsigned FULL = 0xffffffffu;
    int wlo = max(__shfl_sync(FULL, myb, 0)  - 1, 0);
    int whi = min(__shfl_sync(FULL, myb, 31) + 1, NB - 1);

    float mA = FLT_MAX, mB = FLT_MAX;   // alternating min accumulators

    // warp-private staged evaluation of ref points [beg, end)
    auto stage_eval = [&](int beg, int end) {
        for (int base = beg; base < end; base += CAPW) {
            const int take = min(CAPW, end - base);   // warp-uniform
            __syncwarp();
            for (int i = lane; i < take; i += 32)
                sbuf[w][i] = __ldg(rpt + base + i);
            __syncwarp();
            int j = 0;
            for (; j + 8 <= take; j += 8) {
#pragma unroll
                for (int u = 0; u < 8; u += 2) {
                    float4 p  = sbuf[w][j + u];
                    float4 p2 = sbuf[w][j + u + 1];
                    mA = fminf(mA, fmaf(nx, p.x,  fmaf(ny, p.y,  fmaf(nz, p.z,  p.w))));
                    mB = fminf(mB, fmaf(nx, p2.x, fmaf(ny, p2.y, fmaf(nz, p2.z, p2.w))));
                }
            }
            for (; j < take; j++) {
                float4 p = sbuf[w][j];
                mA = fminf(mA, fmaf(nx, p.x, fmaf(ny, p.y, fmaf(nz, p.z, p.w))));
            }
        }
    };

    stage_eval(__ldg(cs + wlo), __ldg(cs + whi + 1));

    const float W = ZSPAN / NB;
    for (;;) {
        float b2 = fminf(mA, mB) + q.w;           // best squared distance
        float le = ZMIN + wlo * W;
        float re = ZMIN + (whi + 1) * W;
        float gl = zq - le, gr = re - zq;
        bool myL = (wlo == 0)      || (gl * gl >= b2);
        bool myR = (whi == NB - 1) || (gr * gr >= b2);
        bool dL = __all_sync(FULL, myL);
        bool dR = __all_sync(FULL, myR);
        if (dL && dR) break;
        if (!dL && !dR) {            // expand both sides in one round
            int nlo = wlo - 1, nhi = whi + 1;
            stage_eval(__ldg(cs + nlo), __ldg(cs + wlo));
            stage_eval(__ldg(cs + whi + 1), __ldg(cs + nhi + 1));
            wlo = nlo; whi = nhi;
        } else if (!dL) {
            wlo--;
            stage_eval(__ldg(cs + wlo), __ldg(cs + wlo + 1));
        } else {
            whi++;
            stage_eval(__ldg(cs + whi), __ldg(cs + whi + 1));
        }
    }

    // deterministic-shape block tree reduction
    __shared__ float sred[QT];
    __shared__ bool  is_last;
    sred[t] = fminf(mA, mB) + q.w;
    __syncthreads();
    for (int s = QT / 2; s > 0; s >>= 1) {
        if (t < s) sred[t] += sred[t + s];
        __syncthreads();
    }

    const int nblk = gridDim.x * gridDim.y * gridDim.z;
    if (t == 0) {
        int bid = (blockIdx.z * gridDim.y + blockIdx.y) * gridDim.x + blockIdx.x;
        g_part[bid] = sred[0];
        __threadfence();
        unsigned int r = atomicAdd(&g_cnt, 1u);
        is_last = (r == (unsigned)(nblk - 1));
    }
    __syncthreads();

    if (is_last) {   // fixed-order final sum (value independent of arrival order)
        float v = 0.f;
        volatile float* vp = g_part;
        for (int i = t; i < nblk; i += QT) v += vp[i];
        sred[t] = v;
        __syncthreads();
        for (int s = QT / 2; s > 0; s >>= 1) {
            if (t < s) sred[t] += sred[t + s];
            __syncthreads();
        }
        if (t == 0) {
            out[0] = sred[0];
            g_cnt = 0;   // reset for next graph replay
        }
    }
}

extern "C" void kernel_launch(void* const* d_in, const int* in_sizes, int n_in,
                              void* d_out, int out_size) {
    const float* preds = (const float*)d_in[0];
    const float* gts   = (const float*)d_in[1];
    float* out = (float*)d_out;
    const int B = in_sizes[0] / (3 * NPTS);  // 8 here

    k_prep<<<2 * B, 256>>>(preds, gts, B);
    k_nop<<<1, 32>>>();
    k_nop<<<1, 32>>>();
    dim3 grid(NPTS / QT, B, 2);              // (32, 8, 2) = 512 blocks
    k_query<<<grid, QT>>>(out, B);           // <- 4th launch: gets the ncu profile
}

// round 12
// speedup vs baseline: 3.6374x; 1.5860x over previous
#include <cuda_runtime.h>
#include <cstdint>
#include <cfloat>

#define NPTS 8192
#define BMAX 8
#define NZ   128
#define NY   32
#define NCELLS (NZ * NY)              // 4096
#define NSB  (2 * BMAX)
#define QT   64                       // 2 autonomous warps per block
#define NW   (QT / 32)
#define CAPW 256                      // per-warp smem slice (float4) = 4KB
#define PT   512                      // prep threads
#define ZMIN (-6.0f)
#define YMIN (-6.0f)
#define SPAN 12.0f
#define WZ   (SPAN / NZ)
#define WY   (SPAN / NY)
#define NQBLK (NPTS / QT * BMAX * 2)  // 2048 query blocks

// ---- scratch (device globals; no allocation) --------------------------------
__device__ float4 g_sorted[NSB * NPTS];        // cell-sorted, w = |p|^2
__device__ int    g_cellstart[NSB * (NCELLS + 1)];
__device__ float  g_part[NQBLK];
__device__ unsigned int g_cnt;                 // zero-init; reset each run

__device__ __forceinline__ int zbucket(float z) {
    int c = (int)((z - ZMIN) * (NZ / SPAN));
    return min(NZ - 1, max(0, c));
}
__device__ __forceinline__ int ybucket(float y) {
    int c = (int)((y - YMIN) * (NY / SPAN));
    return min(NY - 1, max(0, c));
}
// serpentine cell index: odd z-rows store y reversed (query stream stays y-adjacent)
__device__ __forceinline__ int cell_of(int zb, int yb) {
    return zb * NY + ((zb & 1) ? (NY - 1 - yb) : yb);
}

// ==== K1: per set-batch: smem hist -> scan -> scatter ========================
__global__ __launch_bounds__(PT)
void k_prep(const float* __restrict__ preds,
            const float* __restrict__ gts, int B) {
    const int sb  = blockIdx.x;
    const int set = sb / B, b = sb - set * B;
    const float* P = (set == 0 ? preds : gts) + (size_t)b * 3 * NPTS;
    const int t = threadIdx.x;

    __shared__ int s_cnt[NCELLS];
    __shared__ int s_par[PT];

    for (int i = t; i < NCELLS; i += PT) s_cnt[i] = 0;
    __syncthreads();

    for (int i = t; i < NPTS; i += PT) {
        float y = P[NPTS + i], z = P[2 * NPTS + i];
        atomicAdd(&s_cnt[cell_of(zbucket(z), ybucket(y))], 1);
    }
    __syncthreads();

    // per-thread serial over CPT cells + Hillis-Steele over PT partials
    const int CPT = NCELLS / PT;  // 8
    const int first = t * CPT;
    int local = 0;
#pragma unroll
    for (int i = 0; i < CPT; i++) local += s_cnt[first + i];
    s_par[t] = local;
    __syncthreads();
    for (int off = 1; off < PT; off <<= 1) {
        int v = (t >= off) ? s_par[t - off] : 0;
        __syncthreads();
        s_par[t] += v;
        __syncthreads();
    }
    int run = s_par[t] - local;  // exclusive base
    int* cs = g_cellstart + (size_t)sb * (NCELLS + 1);
    int save[CPT];
#pragma unroll
    for (int i = 0; i < CPT; i++) {
        int c = first + i;
        cs[c] = run;
        save[i] = run;
        run += s_cnt[c];
    }
    if (t == PT - 1) cs[NCELLS] = run;  // = NPTS
    __syncthreads();
#pragma unroll
    for (int i = 0; i < CPT; i++) s_cnt[first + i] = save[i];  // running offsets
    __syncthreads();

    float4* dst = g_sorted + (size_t)sb * NPTS;
    for (int i = t; i < NPTS; i += PT) {
        float x = P[i], y = P[NPTS + i], z = P[2 * NPTS + i];
        int pos = atomicAdd(&s_cnt[cell_of(zbucket(z), ybucket(y))], 1);
        dst[pos] = make_float4(x, y, z, x * x + y * y + z * z);
    }
}

// ==== padding so k_query is the 4th launch (ncu profiles launch #4) ==========
__global__ void k_nop() {}

// ==== K2: warp-autonomous 2-D rectangle sweep, per-warp smem staging =========
__global__ __launch_bounds__(QT)
void k_query(float* __restrict__ out, int B) {
    const int b    = blockIdx.y;
    const int dir  = blockIdx.z;
    const int t    = threadIdx.x;
    const int w    = t >> 5;
    const int lane = t & 31;

    const int sbq = (dir == 0 ? 0 : B) + b;
    const int sbr = (dir == 0 ? B : 0) + b;

    const int*    cs  = g_cellstart + (size_t)sbr * (NCELLS + 1);
    const float4* rpt = g_sorted + (size_t)sbr * NPTS;

    const int qidx = blockIdx.x * QT + t;
    float4 q = __ldg(&g_sorted[(size_t)sbq * NPTS + qidx]);
    const float nx = -2.f * q.x, ny = -2.f * q.y, nz = -2.f * q.z;
    const float yq = q.y, zq = q.z;

    const int myzb = zbucket(zq);
    const int myyb = ybucket(yq);

    const unsigned FULL = 0xffffffffu;
    // warp min/max of zb & yb (serpentine breaks lane monotonicity in yb)
    int zlo = myzb, zhi = myzb, ylo = myyb, yhi = myyb;
#pragma unroll
    for (int o = 16; o > 0; o >>= 1) {
        zlo = min(zlo, __shfl_xor_sync(FULL, zlo, o));
        zhi = max(zhi, __shfl_xor_sync(FULL, zhi, o));
        ylo = min(ylo, __shfl_xor_sync(FULL, ylo, o));
        yhi = max(yhi, __shfl_xor_sync(FULL, yhi, o));
    }

    __shared__ float4 sbuf[NW][CAPW];
    float mA = FLT_MAX, mB = FLT_MAX;
    int fill = 0;                      // warp-uniform staging fill

    auto flush = [&]() {
        __syncwarp();
        int j = 0;
        for (; j + 8 <= fill; j += 8) {
#pragma unroll
            for (int u = 0; u < 8; u += 2) {
                float4 p  = sbuf[w][j + u];
                float4 p2 = sbuf[w][j + u + 1];
                mA = fminf(mA, fmaf(nx, p.x,  fmaf(ny, p.y,  fmaf(nz, p.z,  p.w))));
                mB = fminf(mB, fmaf(nx, p2.x, fmaf(ny, p2.y, fmaf(nz, p2.z, p2.w))));
            }
        }
        for (; j < fill; j++) {
            float4 p = sbuf[w][j];
            mA = fminf(mA, fmaf(nx, p.x, fmaf(ny, p.y, fmaf(nz, p.z, p.w))));
        }
        __syncwarp();
        fill = 0;
    };
    auto append = [&](int beg, int end) {   // warp-uniform [beg,end)
        while (beg < end) {
            int take = min(end - beg, CAPW - fill);
            __syncwarp();
            for (int i = lane; i < take; i += 32)
                sbuf[w][fill + i] = __ldg(rpt + beg + i);
            fill += take;
            beg += take;
            if (fill == CAPW) flush();
        }
    };
    // append all cells of z-row zb, actual-y buckets [ya, yb_] (contiguous run)
    auto row = [&](int zb, int ya, int yb_) {
        int c0, c1;
        if (zb & 1) { c0 = zb * NY + (NY - 1 - yb_); c1 = zb * NY + (NY - 1 - ya); }
        else        { c0 = zb * NY + ya;             c1 = zb * NY + yb_;           }
        append(__ldg(cs + c0), __ldg(cs + c1 + 1));
    };

    // initial rectangle = warp's own span
    for (int zb = zlo; zb <= zhi; zb++) row(zb, ylo, yhi);
    flush();

    for (;;) {
        float b2 = fminf(mA, mB) + q.w;    // best squared distance
        float gzl = zq - (ZMIN + zlo * WZ);
        float gzr = (ZMIN + (zhi + 1) * WZ) - zq;
        float gyl = yq - (YMIN + ylo * WY);
        float gyr = (YMIN + (yhi + 1) * WY) - yq;
        bool dZL = (zlo == 0)      || (gzl * gzl >= b2);
        bool dZR = (zhi == NZ - 1) || (gzr * gzr >= b2);
        bool dYL = (ylo == 0)      || (gyl * gyl >= b2);
        bool dYR = (yhi == NY - 1) || (gyr * gyr >= b2);
        bool aZL = __all_sync(FULL, dZL);
        bool aZR = __all_sync(FULL, dZR);
        bool aYL = __all_sync(FULL, dYL);
        bool aYR = __all_sync(FULL, dYR);
        if (aZL && aZR && aYL && aYR) break;

        // Y expansions over the OLD z-range (columns), then Z rows over NEW y-range
        int nylo = ylo, nyhi = yhi;
        if (!aYL) {
            nylo = ylo - 1;
            for (int zb = zlo; zb <= zhi; zb++) row(zb, nylo, nylo);
        }
        if (!aYR) {
            nyhi = yhi + 1;
            for (int zb = zlo; zb <= zhi; zb++) row(zb, nyhi, nyhi);
        }
        ylo = nylo; yhi = nyhi;
        if (!aZL) { zlo--; row(zlo, ylo, yhi); }
        if (!aZR) { zhi++; row(zhi, ylo, yhi); }
        flush();
    }

    // deterministic-shape block tree reduction + fused fixed-order final sum
    __shared__ float sred[QT];
    __shared__ bool  is_last;
    sred[t] = fminf(mA, mB) + q.w;
    __syncthreads();
    for (int s = QT / 2; s > 0; s >>= 1) {
        if (t < s) sred[t] += sred[t + s];
        __syncthreads();
    }

    const int nblk = gridDim.x * gridDim.y * gridDim.z;
    if (t == 0) {
        int bid = (blockIdx.z * gridDim.y + blockIdx.y) * gridDim.x + blockIdx.x;
        g_part[bid] = sred[0];
        __threadfence();
        unsigned int r = atomicAdd(&g_cnt, 1u);
        is_last = (r == (unsigned)(nblk - 1));
    }
    __syncthreads();

    if (is_last) {
        float v = 0.f;
        volatile float* vp = g_part;
        for (int i = t; i < nblk; i += QT) v += vp[i];
        sred[t] = v;
        __syncthreads();
        for (int s = QT / 2; s > 0; s >>= 1) {
            if (t < s) sred[t] += sred[t + s];
            __syncthreads();
        }
        if (t == 0) {
            out[0] = sred[0];
            g_cnt = 0;
        }
    }
}

extern "C" void kernel_launch(void* const* d_in, const int* in_sizes, int n_in,
                              void* d_out, int out_size) {
    const float* preds = (const float*)d_in[0];
    const float* gts   = (const float*)d_in[1];
    float* out = (float*)d_out;
    const int B = in_sizes[0] / (3 * NPTS);  // 8 here

    k_prep<<<2 * B, PT>>>(preds, gts, B);
    k_nop<<<1, 32>>>();
    k_nop<<<1, 32>>>();
    dim3 grid(NPTS / QT, B, 2);              // (128, 8, 2) = 2048 blocks
    k_query<<<grid, QT>>>(out, B);           // <- 4th launch: gets the ncu profile
}